// round 5
// baseline (speedup 1.0000x reference)
#include <cuda_runtime.h>

#define IMG_W   512
#define IMG_HW  (512*512)

__constant__ unsigned char c_lum[64] = {
 16,11,10,16,24,40,51,61, 12,12,14,19,26,58,60,55,
 14,13,16,24,40,57,69,56, 14,17,22,29,51,87,80,62,
 18,22,37,56,68,109,103,77, 24,35,55,64,81,104,113,92,
 49,64,78,87,103,121,120,101, 72,92,95,98,112,100,103,99};
__constant__ unsigned char c_chr[64] = {
 17,18,24,47,99,99,99,99, 18,21,26,66,99,99,99,99,
 24,26,56,99,99,99,99,99, 47,66,99,99,99,99,99,99,
 99,99,99,99,99,99,99,99, 99,99,99,99,99,99,99,99,
 99,99,99,99,99,99,99,99, 99,99,99,99,99,99,99,99};

// 0.5*cos(k*pi/16)
#define C1 0.4903926402016152f
#define C2 0.46193976625564337f
#define C3 0.4157348061512726f
#define C4 0.35355339059327373f
#define C5 0.27778511650980114f
#define C6 0.19134171618254492f
#define C7 0.09754516100806412f

__device__ __forceinline__ void dct8(const float* v, float* o) {
    float s0=v[0]+v[7], s1=v[1]+v[6], s2=v[2]+v[5], s3=v[3]+v[4];
    float d0=v[0]-v[7], d1=v[1]-v[6], d2=v[2]-v[5], d3=v[3]-v[4];
    float pa=s0+s3, pb=s1+s2, ma=s0-s3, mb=s1-s2;
    o[0] = C4*(pa+pb);
    o[4] = C4*(pa-pb);
    o[2] = fmaf(C2, ma,  C6*mb);
    o[6] = fmaf(C6, ma, -C2*mb);
    o[1] = fmaf(C1,d0, fmaf( C3,d1, fmaf( C5,d2,  C7*d3)));
    o[3] = fmaf(C3,d0, fmaf(-C7,d1, fmaf(-C1,d2, -C5*d3)));
    o[5] = fmaf(C5,d0, fmaf(-C1,d1, fmaf( C7,d2,  C3*d3)));
    o[7] = fmaf(C7,d0, fmaf(-C5,d1, fmaf( C3,d2, -C1*d3)));
}

__device__ __forceinline__ void idct8(const float* k, float* v) {
    float t0 = C4*(k[0]+k[4]);
    float t1 = C4*(k[0]-k[4]);
    float r0 = fmaf(C2,k[2],  C6*k[6]);
    float r1 = fmaf(C6,k[2], -C2*k[6]);
    float E0=t0+r0, E1=t1+r1, E2=t1-r1, E3=t0-r0;
    float O0 = fmaf(C1,k[1], fmaf( C3,k[3], fmaf( C5,k[5],  C7*k[7])));
    float O1 = fmaf(C3,k[1], fmaf(-C7,k[3], fmaf(-C1,k[5], -C5*k[7])));
    float O2 = fmaf(C5,k[1], fmaf(-C1,k[3], fmaf( C7,k[5],  C3*k[7])));
    float O3 = fmaf(C7,k[1], fmaf(-C5,k[3], fmaf( C3,k[5], -C1*k[7])));
    v[0]=E0+O0; v[7]=E0-O0;
    v[1]=E1+O1; v[6]=E1-O1;
    v[2]=E2+O2; v[5]=E2-O2;
    v[3]=E3+O3; v[4]=E3-O3;
}

// 8x8 butterfly transpose across 8-lane groups (p = lane&7), regs r[0..7].
// After: (lane p, reg i) holds old (lane i, reg p).
__device__ __forceinline__ void tr8(float* r, int p) {
    #pragma unroll
    for (int m = 1; m < 8; m <<= 1) {
        const bool hi = (p & m) != 0;
        #pragma unroll
        for (int i = 0; i < 8; i++) {
            if (i & m) continue;
            const int j = i | m;
            float s  = hi ? r[i] : r[j];
            float gv = __shfl_xor_sync(0xffffffffu, s, m);
            if (hi) r[i] = gv; else r[j] = gv;
        }
    }
}

// sr*q = K + (0.5 - 1/(exp2(K*qs)+1))*q, qs = (30*log2 e)/q precomputed.
// round(d)==0 proven: |coef|<=4.0, q_min=10 -> |d|<=0.40<0.5.
__device__ __forceinline__ float soft_quant(float K, float qs, float q) {
    float t = K * qs;
    float E;  asm("ex2.approx.f32 %0, %1;" : "=f"(E) : "f"(t));
    float den = E + 1.0f;
    float r;  asm("rcp.approx.f32 %0, %1;" : "=f"(r) : "f"(den));
    return fmaf(0.5f - r, q, K);
}

__global__ void __launch_bounds__(128)
jpeg_kernel(const float* __restrict__ in, float* __restrict__ out)
{
    __shared__ float2 qt[128];      // [0:64) lum, [64:128) chr : {q, 43.28/q}
    const int tid = threadIdx.x;
    {
        int c = tid >> 6, j = tid & 63;
        float q = (float)(c ? c_chr[j] : c_lum[j]);
        qt[tid] = make_float2(q, (1.0f / q) * 43.2808512266689f);
    }
    __syncthreads();

    const int lane = tid & 31;
    const int b    = lane >> 3;       // block within 4-block group
    const int x    = lane & 7;        // row within block (H); transpose index
    const int g    = blockIdx.x * 4 + (tid >> 5);   // 0..1023 per image
    const int brow = g >> 4;          // 0..63
    const int gcol = g & 15;          // 0..15 (32-col group)
    const int ioff = blockIdx.y * (3*IMG_HW) + (brow*8 + x)*IMG_W + gcol*32 + b*8;
    const float* p = in + ioff;

    // ---- load rows of 4 blocks, 3 channels ----
    float4 ra = *(const float4*)(p),            rb = *(const float4*)(p + 4);
    float4 ga = *(const float4*)(p + IMG_HW),   gb = *(const float4*)(p + IMG_HW + 4);
    float4 ba = *(const float4*)(p + 2*IMG_HW), bb = *(const float4*)(p + 2*IMG_HW + 4);
    float R[8]  = {ra.x,ra.y,ra.z,ra.w, rb.x,rb.y,rb.z,rb.w};
    float G[8]  = {ga.x,ga.y,ga.z,ga.w, gb.x,gb.y,gb.z,gb.w};
    float Bc[8] = {ba.x,ba.y,ba.z,ba.w, bb.x,bb.y,bb.z,bb.w};

    // ---- forward color + row-DCT (along y) ----
    float Y[8], Cb[8], Cr[8];
    {
        float t[8];
        #pragma unroll
        for (int y = 0; y < 8; y++)
            t[y] = fmaf(0.299f, R[y], fmaf(0.587f, G[y], 0.114f*Bc[y])) - 0.5f;
        dct8(t, Y);
        #pragma unroll
        for (int y = 0; y < 8; y++)
            t[y] = fmaf(-0.168736f, R[y], fmaf(-0.331264f, G[y], 0.5f*Bc[y]));
        dct8(t, Cb);
        #pragma unroll
        for (int y = 0; y < 8; y++)
            t[y] = fmaf(0.5f, R[y], fmaf(-0.418688f, G[y], -0.081312f*Bc[y]));
        dct8(t, Cr);
    }

    // ---- transpose: lane becomes v, regs become x ----
    tr8(Y, x); tr8(Cb, x); tr8(Cr, x);

    // ---- column-DCT + quant/tanh/dequant + column-IDCT (all in regs) ----
    {
        float tA[8], tB[8], tC[8];
        dct8(Y,  tA);
        dct8(Cb, tB);
        dct8(Cr, tC);
        #pragma unroll
        for (int u = 0; u < 8; u++) {
            float2 ql = qt[u*8 + x];        // lane index x now means v
            float2 qc = qt[64 + u*8 + x];
            tA[u] = soft_quant(tA[u], ql.y, ql.x);
            tB[u] = soft_quant(tB[u], qc.y, qc.x);
            tC[u] = soft_quant(tC[u], qc.y, qc.x);
        }
        idct8(tA, Y);
        idct8(tB, Cb);
        idct8(tC, Cr);
    }

    // ---- transpose back: lane = x, regs = v ----
    tr8(Y, x); tr8(Cb, x); tr8(Cr, x);

    // ---- row-IDCT + inverse color + clip + store ----
    {
        float yv[8], cbv[8], crv[8];
        idct8(Y,  yv);
        idct8(Cb, cbv);
        idct8(Cr, crv);

        float Ro[8], Go[8], Bo[8];
        #pragma unroll
        for (int y = 0; y < 8; y++) {
            float Yp = yv[y] + 0.5f;
            float cb = cbv[y];
            float cr = crv[y];
            Ro[y] = __saturatef(fmaf(1.402f, cr, Yp));
            Go[y] = __saturatef(fmaf(-0.344136f, cb, fmaf(-0.714136f, cr, Yp)));
            Bo[y] = __saturatef(fmaf(1.772f, cb, Yp));
        }
        float* q0 = out + ioff;
        *(float4*)(q0)                  = make_float4(Ro[0],Ro[1],Ro[2],Ro[3]);
        *(float4*)(q0 + 4)              = make_float4(Ro[4],Ro[5],Ro[6],Ro[7]);
        *(float4*)(q0 + IMG_HW)         = make_float4(Go[0],Go[1],Go[2],Go[3]);
        *(float4*)(q0 + IMG_HW + 4)     = make_float4(Go[4],Go[5],Go[6],Go[7]);
        *(float4*)(q0 + 2*IMG_HW)       = make_float4(Bo[0],Bo[1],Bo[2],Bo[3]);
        *(float4*)(q0 + 2*IMG_HW + 4)   = make_float4(Bo[4],Bo[5],Bo[6],Bo[7]);
    }
}

extern "C" void kernel_launch(void* const* d_in, const int* in_sizes, int n_in,
                              void* d_out, int out_size)
{
    const float* in = (const float*)d_in[0];
    float* out = (float*)d_out;
    dim3 grid(256, 32);   // 256 CTAs x 4 warps = 1024 block-groups per image
    jpeg_kernel<<<grid, 128>>>(in, out);
}

// round 6
// speedup vs baseline: 1.3325x; 1.3325x over previous
#include <cuda_runtime.h>

#define IMG_W   512
#define IMG_HW  (512*512)
#define BLK12   12                // floats per 8-col block (8 data + 4 pad, 16B-aligned)
#define NBLK    16                // blocks per 128-wide strip
#define RW      (NBLK*BLK12)      // 192 floats per row per channel
#define CHS     (8*RW)            // 1536 floats per channel
#define QOFF    (3*CHS)           // 4608
#define SMEM_FLOATS (QOFF + 256)  // + float2 qtab[128]

__constant__ unsigned char c_lum[64] = {
 16,11,10,16,24,40,51,61, 12,12,14,19,26,58,60,55,
 14,13,16,24,40,57,69,56, 14,17,22,29,51,87,80,62,
 18,22,37,56,68,109,103,77, 24,35,55,64,81,104,113,92,
 49,64,78,87,103,121,120,101, 72,92,95,98,112,100,103,99};
__constant__ unsigned char c_chr[64] = {
 17,18,24,47,99,99,99,99, 18,21,26,66,99,99,99,99,
 24,26,56,99,99,99,99,99, 47,66,99,99,99,99,99,99,
 99,99,99,99,99,99,99,99, 99,99,99,99,99,99,99,99,
 99,99,99,99,99,99,99,99, 99,99,99,99,99,99,99,99};

// 0.5*cos(k*pi/16)
#define C1 0.4903926402016152f
#define C2 0.46193976625564337f
#define C3 0.4157348061512726f
#define C4 0.35355339059327373f
#define C5 0.27778511650980114f
#define C6 0.19134171618254492f
#define C7 0.09754516100806412f

__device__ __forceinline__ void dct8(const float* v, float* o) {
    float s0=v[0]+v[7], s1=v[1]+v[6], s2=v[2]+v[5], s3=v[3]+v[4];
    float d0=v[0]-v[7], d1=v[1]-v[6], d2=v[2]-v[5], d3=v[3]-v[4];
    float pa=s0+s3, pb=s1+s2, ma=s0-s3, mb=s1-s2;
    o[0] = C4*(pa+pb);
    o[4] = C4*(pa-pb);
    o[2] = fmaf(C2, ma,  C6*mb);
    o[6] = fmaf(C6, ma, -C2*mb);
    o[1] = fmaf(C1,d0, fmaf( C3,d1, fmaf( C5,d2,  C7*d3)));
    o[3] = fmaf(C3,d0, fmaf(-C7,d1, fmaf(-C1,d2, -C5*d3)));
    o[5] = fmaf(C5,d0, fmaf(-C1,d1, fmaf( C7,d2,  C3*d3)));
    o[7] = fmaf(C7,d0, fmaf(-C5,d1, fmaf( C3,d2, -C1*d3)));
}

__device__ __forceinline__ void idct8(const float* k, float* v) {
    float t0 = C4*(k[0]+k[4]);
    float t1 = C4*(k[0]-k[4]);
    float r0 = fmaf(C2,k[2],  C6*k[6]);
    float r1 = fmaf(C6,k[2], -C2*k[6]);
    float E0=t0+r0, E1=t1+r1, E2=t1-r1, E3=t0-r0;
    float O0 = fmaf(C1,k[1], fmaf( C3,k[3], fmaf( C5,k[5],  C7*k[7])));
    float O1 = fmaf(C3,k[1], fmaf(-C7,k[3], fmaf(-C1,k[5], -C5*k[7])));
    float O2 = fmaf(C5,k[1], fmaf(-C1,k[3], fmaf( C7,k[5],  C3*k[7])));
    float O3 = fmaf(C7,k[1], fmaf(-C5,k[3], fmaf( C3,k[5], -C1*k[7])));
    v[0]=E0+O0; v[7]=E0-O0;
    v[1]=E1+O1; v[6]=E1-O1;
    v[2]=E2+O2; v[5]=E2-O2;
    v[3]=E3+O3; v[4]=E3-O3;
}

// sr*q = K + (0.5 - 1/(exp2(K*qs)+1))*q,  qs = (30*log2 e)/q precomputed.
// round(d)==0 proven: |coef| <= 4.0, q_min = 10 -> |d| <= 0.40 < 0.5.
// MUFU (ex2 + rcp) keeps this off the FMA pipe: 2 MUFU + 4 fma-pipe ops.
__device__ __forceinline__ float soft_quant(float K, float qs, float q) {
    float t = K * qs;
    float E;  asm("ex2.approx.f32 %0, %1;" : "=f"(E) : "f"(t));
    float den = E + 1.0f;
    float r;  asm("rcp.approx.f32 %0, %1;" : "=f"(r) : "f"(den));
    return fmaf(0.5f - r, q, K);
}

__global__ void __launch_bounds__(128, 10)
jpeg_kernel(const float* __restrict__ in, float* __restrict__ out)
{
    __shared__ float sm[SMEM_FLOATS];
    float2* qt = (float2*)(sm + QOFF);   // [0:64) lum, [64:128) chr : {q, 43.28/q}

    const int tid = threadIdx.x;
    const int sx  = blockIdx.x & 3;          // which 128-col strip
    const int sy  = blockIdx.x >> 2;         // which 8-row strip
    const int base = blockIdx.y * (3*IMG_HW) + sy * (8*IMG_W) + sx * 128;

    {
        int c = tid >> 6, j = tid & 63;
        float q = (float)(c ? c_chr[j] : c_lum[j]);
        qt[tid] = make_float2(q, (1.0f / q) * 43.2808512266689f);
    }

    // ---- P1: load + forward color + row-DCT (along y) -> smem (STS.128) ----
    {
        const int x   = tid >> 4;
        const int blk = tid & 15;
        const int gi  = base + x*IMG_W + blk*8;
        const float4* p0 = (const float4*)(in + gi);
        const float4* p1 = (const float4*)(in + gi + IMG_HW);
        const float4* p2 = (const float4*)(in + gi + 2*IMG_HW);
        float4 ra = p0[0], rb = p0[1];
        float4 ga = p1[0], gb = p1[1];
        float4 ba = p2[0], bb = p2[1];
        float r[8]  = {ra.x,ra.y,ra.z,ra.w, rb.x,rb.y,rb.z,rb.w};
        float g[8]  = {ga.x,ga.y,ga.z,ga.w, gb.x,gb.y,gb.z,gb.w};
        float bl[8] = {ba.x,ba.y,ba.z,ba.w, bb.x,bb.y,bb.z,bb.w};

        const int soff = x*RW + blk*BLK12;
        float a[8], o[8];
        #pragma unroll
        for (int y = 0; y < 8; y++)
            a[y] = fmaf(0.299f, r[y], fmaf(0.587f, g[y], 0.114f*bl[y])) - 0.5f;
        dct8(a, o);
        *(float4*)(sm + soff)     = make_float4(o[0],o[1],o[2],o[3]);
        *(float4*)(sm + soff + 4) = make_float4(o[4],o[5],o[6],o[7]);

        #pragma unroll
        for (int y = 0; y < 8; y++)
            a[y] = fmaf(-0.168736f, r[y], fmaf(-0.331264f, g[y], 0.5f*bl[y]));
        dct8(a, o);
        *(float4*)(sm + CHS + soff)     = make_float4(o[0],o[1],o[2],o[3]);
        *(float4*)(sm + CHS + soff + 4) = make_float4(o[4],o[5],o[6],o[7]);

        #pragma unroll
        for (int y = 0; y < 8; y++)
            a[y] = fmaf(0.5f, r[y], fmaf(-0.418688f, g[y], -0.081312f*bl[y]));
        dct8(a, o);
        *(float4*)(sm + 2*CHS + soff)     = make_float4(o[0],o[1],o[2],o[3]);
        *(float4*)(sm + 2*CHS + soff + 4) = make_float4(o[4],o[5],o[6],o[7]);
    }
    __syncthreads();

    // ---- P2: column-DCT + quant/tanh/dequant + column-IDCT, in place ----
    {
        const int v   = tid & 7;
        const int blk = tid >> 3;            // 0..15
        #pragma unroll
        for (int c = 0; c < 3; c++) {
            const int coff = c*CHS + blk*BLK12 + v;
            float k[8], K[8], z[8];
            #pragma unroll
            for (int x = 0; x < 8; x++) k[x] = sm[coff + x*RW];
            dct8(k, K);
            const int qb = (c ? 64 : 0) + v;
            #pragma unroll
            for (int u = 0; u < 8; u++) {
                float2 qq = qt[qb + u*8];
                K[u] = soft_quant(K[u], qq.y, qq.x);
            }
            idct8(K, z);
            #pragma unroll
            for (int x = 0; x < 8; x++) sm[coff + x*RW] = z[x];
        }
    }
    __syncthreads();

    // ---- P3: row-IDCT (LDS.128) + inverse color + clip + stores ----
    {
        const int x   = tid >> 4;
        const int blk = tid & 15;
        const int soff = x*RW + blk*BLK12;
        float z[8], rec0[8], rec1[8], rec2[8];
        {
            float4 za = *(const float4*)(sm + soff);
            float4 zb = *(const float4*)(sm + soff + 4);
            z[0]=za.x; z[1]=za.y; z[2]=za.z; z[3]=za.w;
            z[4]=zb.x; z[5]=zb.y; z[6]=zb.z; z[7]=zb.w;
        }
        idct8(z, rec0);
        {
            float4 za = *(const float4*)(sm + CHS + soff);
            float4 zb = *(const float4*)(sm + CHS + soff + 4);
            z[0]=za.x; z[1]=za.y; z[2]=za.z; z[3]=za.w;
            z[4]=zb.x; z[5]=zb.y; z[6]=zb.z; z[7]=zb.w;
        }
        idct8(z, rec1);
        {
            float4 za = *(const float4*)(sm + 2*CHS + soff);
            float4 zb = *(const float4*)(sm + 2*CHS + soff + 4);
            z[0]=za.x; z[1]=za.y; z[2]=za.z; z[3]=za.w;
            z[4]=zb.x; z[5]=zb.y; z[6]=zb.z; z[7]=zb.w;
        }
        idct8(z, rec2);

        float R[8], G[8], B[8];
        #pragma unroll
        for (int y = 0; y < 8; y++) {
            float Y  = rec0[y] + 0.5f;
            float cb = rec1[y];
            float cr = rec2[y];
            R[y] = __saturatef(fmaf(1.402f, cr, Y));
            G[y] = __saturatef(fmaf(-0.344136f, cb, fmaf(-0.714136f, cr, Y)));
            B[y] = __saturatef(fmaf(1.772f, cb, Y));
        }
        const int go = base + x*IMG_W + blk*8;
        float4* p0 = (float4*)(out + go);
        float4* p1 = (float4*)(out + go + IMG_HW);
        float4* p2 = (float4*)(out + go + 2*IMG_HW);
        p0[0] = make_float4(R[0],R[1],R[2],R[3]);
        p0[1] = make_float4(R[4],R[5],R[6],R[7]);
        p1[0] = make_float4(G[0],G[1],G[2],G[3]);
        p1[1] = make_float4(G[4],G[5],G[6],G[7]);
        p2[0] = make_float4(B[0],B[1],B[2],B[3]);
        p2[1] = make_float4(B[4],B[5],B[6],B[7]);
    }
}

extern "C" void kernel_launch(void* const* d_in, const int* in_sizes, int n_in,
                              void* d_out, int out_size)
{
    const float* in = (const float*)d_in[0];
    float* out = (float*)d_out;
    dim3 grid(256, 32);   // 4 col-strips x 64 row-strips, 32 images
    jpeg_kernel<<<grid, 128>>>(in, out);
}

// round 7
// speedup vs baseline: 1.4009x; 1.0513x over previous
#include <cuda_runtime.h>

#define IMG_W   512
#define IMG_HW  (512*512)
#define BLK12   12                // floats per 8-col block (8 data + 4 pad, 16B-aligned)
#define NBLK    16                // blocks per 128-wide strip
#define RW      (NBLK*BLK12)      // 192 floats per row per channel
#define CHS     (8*RW)            // 1536 floats per channel
#define QOFF    (3*CHS)           // 4608
#define SMEM_FLOATS (QOFF + 256)  // + float2 qtab[128]

__constant__ unsigned char c_lum[64] = {
 16,11,10,16,24,40,51,61, 12,12,14,19,26,58,60,55,
 14,13,16,24,40,57,69,56, 14,17,22,29,51,87,80,62,
 18,22,37,56,68,109,103,77, 24,35,55,64,81,104,113,92,
 49,64,78,87,103,121,120,101, 72,92,95,98,112,100,103,99};
__constant__ unsigned char c_chr[64] = {
 17,18,24,47,99,99,99,99, 18,21,26,66,99,99,99,99,
 24,26,56,99,99,99,99,99, 47,66,99,99,99,99,99,99,
 99,99,99,99,99,99,99,99, 99,99,99,99,99,99,99,99,
 99,99,99,99,99,99,99,99, 99,99,99,99,99,99,99,99};

// 0.5*cos(k*pi/16)
#define C1 0.4903926402016152f
#define C2 0.46193976625564337f
#define C3 0.4157348061512726f
#define C4 0.35355339059327373f
#define C5 0.27778511650980114f
#define C6 0.19134171618254492f
#define C7 0.09754516100806412f

__device__ __forceinline__ void dct8(const float* v, float* o) {
    float s0=v[0]+v[7], s1=v[1]+v[6], s2=v[2]+v[5], s3=v[3]+v[4];
    float d0=v[0]-v[7], d1=v[1]-v[6], d2=v[2]-v[5], d3=v[3]-v[4];
    float pa=s0+s3, pb=s1+s2, ma=s0-s3, mb=s1-s2;
    o[0] = C4*(pa+pb);
    o[4] = C4*(pa-pb);
    o[2] = fmaf(C2, ma,  C6*mb);
    o[6] = fmaf(C6, ma, -C2*mb);
    o[1] = fmaf(C1,d0, fmaf( C3,d1, fmaf( C5,d2,  C7*d3)));
    o[3] = fmaf(C3,d0, fmaf(-C7,d1, fmaf(-C1,d2, -C5*d3)));
    o[5] = fmaf(C5,d0, fmaf(-C1,d1, fmaf( C7,d2,  C3*d3)));
    o[7] = fmaf(C7,d0, fmaf(-C5,d1, fmaf( C3,d2, -C1*d3)));
}

__device__ __forceinline__ void idct8(const float* k, float* v) {
    float t0 = C4*(k[0]+k[4]);
    float t1 = C4*(k[0]-k[4]);
    float r0 = fmaf(C2,k[2],  C6*k[6]);
    float r1 = fmaf(C6,k[2], -C2*k[6]);
    float E0=t0+r0, E1=t1+r1, E2=t1-r1, E3=t0-r0;
    float O0 = fmaf(C1,k[1], fmaf( C3,k[3], fmaf( C5,k[5],  C7*k[7])));
    float O1 = fmaf(C3,k[1], fmaf(-C7,k[3], fmaf(-C1,k[5], -C5*k[7])));
    float O2 = fmaf(C5,k[1], fmaf(-C1,k[3], fmaf( C7,k[5],  C3*k[7])));
    float O3 = fmaf(C7,k[1], fmaf(-C5,k[3], fmaf( C3,k[5], -C1*k[7])));
    v[0]=E0+O0; v[7]=E0-O0;
    v[1]=E1+O1; v[6]=E1-O1;
    v[2]=E2+O2; v[5]=E2-O2;
    v[3]=E3+O3; v[4]=E3-O3;
}

// sr*q = K + (0.5 - 1/(exp2(K*qs)+1))*q,  qs = (30*log2 e)/q precomputed.
// round(d)==0 proven: |coef| <= 4.0, q_min = 10 -> |d| <= 0.40 < 0.5.
// MUFU (ex2 + rcp) keeps this off the FMA pipe: 2 MUFU + 4 fma-pipe ops.
__device__ __forceinline__ float soft_quant(float K, float qs, float q) {
    float t = K * qs;
    float E;  asm("ex2.approx.f32 %0, %1;" : "=f"(E) : "f"(t));
    float den = E + 1.0f;
    float r;  asm("rcp.approx.f32 %0, %1;" : "=f"(r) : "f"(den));
    return fmaf(0.5f - r, q, K);
}

__global__ void __launch_bounds__(128, 8)
jpeg_kernel(const float* __restrict__ in, float* __restrict__ out)
{
    __shared__ float sm[SMEM_FLOATS];
    float2* qt = (float2*)(sm + QOFF);   // [c2][u][v] : {q, 43.28/q}

    const int tid = threadIdx.x;
    const int sx  = blockIdx.x & 3;          // which 128-col strip
    const int sy  = blockIdx.x >> 2;         // which 8-row strip
    const int base = blockIdx.y * (3*IMG_HW) + sy * (8*IMG_W) + sx * 128;

    {
        int c = tid >> 6, j = tid & 63;
        float q = (float)(c ? c_chr[j] : c_lum[j]);
        qt[tid] = make_float2(q, (1.0f / q) * 43.2808512266689f);
    }

    // ---- P1: load + forward color + row-DCT (along y) -> smem (STS.128) ----
    {
        const int x   = tid >> 4;
        const int blk = tid & 15;
        const int gi  = base + x*IMG_W + blk*8;
        const float4* p0 = (const float4*)(in + gi);
        const float4* p1 = (const float4*)(in + gi + IMG_HW);
        const float4* p2 = (const float4*)(in + gi + 2*IMG_HW);
        float4 ra = p0[0], rb = p0[1];
        float4 ga = p1[0], gb = p1[1];
        float4 ba = p2[0], bb = p2[1];
        float r[8]  = {ra.x,ra.y,ra.z,ra.w, rb.x,rb.y,rb.z,rb.w};
        float g[8]  = {ga.x,ga.y,ga.z,ga.w, gb.x,gb.y,gb.z,gb.w};
        float bl[8] = {ba.x,ba.y,ba.z,ba.w, bb.x,bb.y,bb.z,bb.w};

        const int soff = x*RW + blk*BLK12;
        float a[8], o[8];
        #pragma unroll
        for (int y = 0; y < 8; y++)
            a[y] = fmaf(0.299f, r[y], fmaf(0.587f, g[y], 0.114f*bl[y])) - 0.5f;
        dct8(a, o);
        *(float4*)(sm + soff)     = make_float4(o[0],o[1],o[2],o[3]);
        *(float4*)(sm + soff + 4) = make_float4(o[4],o[5],o[6],o[7]);

        #pragma unroll
        for (int y = 0; y < 8; y++)
            a[y] = fmaf(-0.168736f, r[y], fmaf(-0.331264f, g[y], 0.5f*bl[y]));
        dct8(a, o);
        *(float4*)(sm + CHS + soff)     = make_float4(o[0],o[1],o[2],o[3]);
        *(float4*)(sm + CHS + soff + 4) = make_float4(o[4],o[5],o[6],o[7]);

        #pragma unroll
        for (int y = 0; y < 8; y++)
            a[y] = fmaf(0.5f, r[y], fmaf(-0.418688f, g[y], -0.081312f*bl[y]));
        dct8(a, o);
        *(float4*)(sm + 2*CHS + soff)     = make_float4(o[0],o[1],o[2],o[3]);
        *(float4*)(sm + 2*CHS + soff + 4) = make_float4(o[4],o[5],o[6],o[7]);
    }
    __syncthreads();

    // ---- P2: vectorized. One thread = one 4-column slab (c, blk, half).
    //      96 active threads: 8 LDS.128 + 8 STS.128 instead of 4x16 scalar.
    if (tid < 96) {
        const int c    = tid >> 5;           // channel 0..2
        const int sub  = tid & 31;
        const int blk  = sub >> 1;           // 0..15
        const int half = sub & 1;            // 0..1 -> v in [half*4, half*4+4)
        float* bp = sm + c*CHS + blk*BLK12 + half*4;

        float m[32];                         // [x][j], j = v - half*4
        #pragma unroll
        for (int x = 0; x < 8; x++) {
            float4 w = *(const float4*)(bp + x*RW);
            m[x*4+0]=w.x; m[x*4+1]=w.y; m[x*4+2]=w.z; m[x*4+3]=w.w;
        }
        // 4 column DCTs (in place; dct8 reads all inputs before writing)
        #pragma unroll
        for (int j = 0; j < 4; j++) {
            float k[8], K[8];
            #pragma unroll
            for (int x = 0; x < 8; x++) k[x] = m[x*4+j];
            dct8(k, K);
            #pragma unroll
            for (int u = 0; u < 8; u++) m[u*4+j] = K[u];
        }
        // quant/tanh/dequant: 2 broadcast LDS.128 per u
        const float4* q4 = (const float4*)qt;
        const int qbase = (c ? 32 : 0) + half*2;   // float4 index: c2*32 + u*4 + half*2
        #pragma unroll
        for (int u = 0; u < 8; u++) {
            float4 qa = q4[qbase + u*4];
            float4 qb = q4[qbase + u*4 + 1];
            m[u*4+0] = soft_quant(m[u*4+0], qa.y, qa.x);
            m[u*4+1] = soft_quant(m[u*4+1], qa.w, qa.z);
            m[u*4+2] = soft_quant(m[u*4+2], qb.y, qb.x);
            m[u*4+3] = soft_quant(m[u*4+3], qb.w, qb.z);
        }
        // 4 column IDCTs
        #pragma unroll
        for (int j = 0; j < 4; j++) {
            float k[8], z[8];
            #pragma unroll
            for (int u = 0; u < 8; u++) k[u] = m[u*4+j];
            idct8(k, z);
            #pragma unroll
            for (int x = 0; x < 8; x++) m[x*4+j] = z[x];
        }
        #pragma unroll
        for (int x = 0; x < 8; x++)
            *(float4*)(bp + x*RW) = make_float4(m[x*4],m[x*4+1],m[x*4+2],m[x*4+3]);
    }
    __syncthreads();

    // ---- P3: row-IDCT (LDS.128) + inverse color + clip + stores ----
    {
        const int x   = tid >> 4;
        const int blk = tid & 15;
        const int soff = x*RW + blk*BLK12;
        float z[8], rec0[8], rec1[8], rec2[8];
        {
            float4 za = *(const float4*)(sm + soff);
            float4 zb = *(const float4*)(sm + soff + 4);
            z[0]=za.x; z[1]=za.y; z[2]=za.z; z[3]=za.w;
            z[4]=zb.x; z[5]=zb.y; z[6]=zb.z; z[7]=zb.w;
        }
        idct8(z, rec0);
        {
            float4 za = *(const float4*)(sm + CHS + soff);
            float4 zb = *(const float4*)(sm + CHS + soff + 4);
            z[0]=za.x; z[1]=za.y; z[2]=za.z; z[3]=za.w;
            z[4]=zb.x; z[5]=zb.y; z[6]=zb.z; z[7]=zb.w;
        }
        idct8(z, rec1);
        {
            float4 za = *(const float4*)(sm + 2*CHS + soff);
            float4 zb = *(const float4*)(sm + 2*CHS + soff + 4);
            z[0]=za.x; z[1]=za.y; z[2]=za.z; z[3]=za.w;
            z[4]=zb.x; z[5]=zb.y; z[6]=zb.z; z[7]=zb.w;
        }
        idct8(z, rec2);

        float R[8], G[8], B[8];
        #pragma unroll
        for (int y = 0; y < 8; y++) {
            float Y  = rec0[y] + 0.5f;
            float cb = rec1[y];
            float cr = rec2[y];
            R[y] = __saturatef(fmaf(1.402f, cr, Y));
            G[y] = __saturatef(fmaf(-0.344136f, cb, fmaf(-0.714136f, cr, Y)));
            B[y] = __saturatef(fmaf(1.772f, cb, Y));
        }
        const int go = base + x*IMG_W + blk*8;
        float4* p0 = (float4*)(out + go);
        float4* p1 = (float4*)(out + go + IMG_HW);
        float4* p2 = (float4*)(out + go + 2*IMG_HW);
        p0[0] = make_float4(R[0],R[1],R[2],R[3]);
        p0[1] = make_float4(R[4],R[5],R[6],R[7]);
        p1[0] = make_float4(G[0],G[1],G[2],G[3]);
        p1[1] = make_float4(G[4],G[5],G[6],G[7]);
        p2[0] = make_float4(B[0],B[1],B[2],B[3]);
        p2[1] = make_float4(B[4],B[5],B[6],B[7]);
    }
}

extern "C" void kernel_launch(void* const* d_in, const int* in_sizes, int n_in,
                              void* d_out, int out_size)
{
    const float* in = (const float*)d_in[0];
    float* out = (float*)d_out;
    dim3 grid(256, 32);   // 4 col-strips x 64 row-strips, 32 images
    jpeg_kernel<<<grid, 128>>>(in, out);
}